// round 5
// baseline (speedup 1.0000x reference)
#include <cuda_runtime.h>
#include <math.h>

// Problem constants (GroupedSwiGLUExperts)
#define TOK_M   2048
#define DIM_K   2048
#define DIM_N   1408
#define NEXP    8
#define TOPK    2
#define NROWS   (TOK_M * TOPK)   // 4096 routed rows

// SGEMM tiling
#define BM 64
#define BN 64
#define BK 16

// ---------------------------------------------------------------------------
// Device scratch (no allocations allowed anywhere)
// ---------------------------------------------------------------------------
__device__ int   g_sorted_row[NROWS];               // sorted position -> routed row r (r = token*TOPK + slot)
__device__ int   g_counts[NEXP];
__device__ int   g_starts[NEXP];
__device__ float g_hbuf[(size_t)NROWS * DIM_N];     // SwiGLU intermediate, indexed by sorted position

// ---------------------------------------------------------------------------
// Kernel 1: routing — stable counting sort of routed rows by expert id.
// Single block, 256 threads, 16 rows/thread.
// ---------------------------------------------------------------------------
__global__ void route_kernel(const int* __restrict__ flat_idx) {
    __shared__ int sh_cnt[256][NEXP];   // per-thread-chunk exclusive offsets after scan
    __shared__ int sh_tot[NEXP];
    __shared__ int sh_start[NEXP];

    const int t    = threadIdx.x;
    const int per  = NROWS / 256;       // 16
    const int base = t * per;

    int local[NEXP];
#pragma unroll
    for (int e = 0; e < NEXP; e++) local[e] = 0;
    for (int i = 0; i < per; i++) local[flat_idx[base + i]]++;
#pragma unroll
    for (int e = 0; e < NEXP; e++) sh_cnt[t][e] = local[e];
    __syncthreads();

    // Exclusive scan across the 256 chunks, one expert per thread (E=8).
    if (t < NEXP) {
        int run = 0;
        for (int u = 0; u < 256; u++) {
            int v = sh_cnt[u][t];
            sh_cnt[u][t] = run;
            run += v;
        }
        sh_tot[t] = run;
    }
    __syncthreads();

    if (t == 0) {
        int run = 0;
        for (int e = 0; e < NEXP; e++) {
            sh_start[e]  = run;
            g_starts[e]  = run;
            g_counts[e]  = sh_tot[e];
            run += sh_tot[e];
        }
    }
    __syncthreads();

    int off[NEXP];
#pragma unroll
    for (int e = 0; e < NEXP; e++) off[e] = sh_start[e] + sh_cnt[t][e];
    for (int i = 0; i < per; i++) {
        int e = flat_idx[base + i];
        g_sorted_row[off[e]++] = base + i;   // stable within chunk, stable across by scan
    }
}

// ---------------------------------------------------------------------------
// Kernel 2: zero the output (harness poisons it with 0xAA)
// ---------------------------------------------------------------------------
__global__ void zero_kernel(float4* __restrict__ p, int n4) {
    int i = blockIdx.x * blockDim.x + threadIdx.x;
    if (i < n4) p[i] = make_float4(0.f, 0.f, 0.f, 0.f);
}

// ---------------------------------------------------------------------------
// Kernel 3: fused gate/up GEMM + SwiGLU.
//   For expert e, rows c in [0, cnt):  g = A·Gw^T, u = A·Uw^T,
//   h = silu(min(g,10)) * clip(u,-10,10)  -> g_hbuf[sorted_pos][n]
// A rows are gathered from flat_h via the routing tables.
// Tile: 64x64x16, 256 threads, 4x4 microtile, dual accumulators.
// ---------------------------------------------------------------------------
__global__ __launch_bounds__(256)
void gemm1_swiglu_kernel(const float* __restrict__ flat_h,
                         const float* __restrict__ gate_w,
                         const float* __restrict__ up_w) {
    const int e   = blockIdx.z;
    const int cnt = g_counts[e];
    const int m0  = blockIdx.y * BM;
    if (m0 >= cnt) return;
    const int n0    = blockIdx.x * BN;
    const int start = g_starts[e];

    const int tid = threadIdx.x;
    const int tx  = tid & 15;        // output col group
    const int ty  = tid >> 4;        // output row group
    const int lr  = tid >> 2;        // load row (0..63)
    const int lq  = tid & 3;         // load k-quad (0..3)

    __shared__ float As[BK][BM];
    __shared__ float Bg[BK][BN];
    __shared__ float Bu[BK][BN];
    __shared__ int   sh_tok[BM];

    if (tid < BM) {
        int m = m0 + tid;
        sh_tok[tid] = (m < cnt) ? (g_sorted_row[start + m] >> 1) : -1;  // token = r / TOPK
    }
    __syncthreads();

    const int  tokr   = sh_tok[lr];
    const bool avalid = (tokr >= 0);
    const float* aptr = flat_h + (size_t)(avalid ? tokr : 0) * DIM_K + lq * 4;
    const float* gptr = gate_w + ((size_t)e * DIM_N + n0 + lr) * DIM_K + lq * 4;
    const float* uptr = up_w   + ((size_t)e * DIM_N + n0 + lr) * DIM_K + lq * 4;

    float accG[4][4];
    float accU[4][4];
#pragma unroll
    for (int i = 0; i < 4; i++)
#pragma unroll
        for (int j = 0; j < 4; j++) { accG[i][j] = 0.f; accU[i][j] = 0.f; }

    for (int k0 = 0; k0 < DIM_K; k0 += BK) {
        float4 av = avalid ? *(const float4*)(aptr + k0) : make_float4(0.f, 0.f, 0.f, 0.f);
        float4 gv = *(const float4*)(gptr + k0);
        float4 uv = *(const float4*)(uptr + k0);
        const int kk = lq * 4;
        As[kk + 0][lr] = av.x; As[kk + 1][lr] = av.y; As[kk + 2][lr] = av.z; As[kk + 3][lr] = av.w;
        Bg[kk + 0][lr] = gv.x; Bg[kk + 1][lr] = gv.y; Bg[kk + 2][lr] = gv.z; Bg[kk + 3][lr] = gv.w;
        Bu[kk + 0][lr] = uv.x; Bu[kk + 1][lr] = uv.y; Bu[kk + 2][lr] = uv.z; Bu[kk + 3][lr] = uv.w;
        __syncthreads();

#pragma unroll
        for (int k = 0; k < BK; k++) {
            float4 a4 = *(const float4*)&As[k][ty * 4];
            float4 g4 = *(const float4*)&Bg[k][tx * 4];
            float4 u4 = *(const float4*)&Bu[k][tx * 4];
            float rA[4] = {a4.x, a4.y, a4.z, a4.w};
            float rG[4] = {g4.x, g4.y, g4.z, g4.w};
            float rU[4] = {u4.x, u4.y, u4.z, u4.w};
#pragma unroll
            for (int i = 0; i < 4; i++)
#pragma unroll
                for (int j = 0; j < 4; j++) {
                    accG[i][j] += rA[i] * rG[j];
                    accU[i][j] += rA[i] * rU[j];
                }
        }
        __syncthreads();
    }

    // Fused SwiGLU epilogue -> g_hbuf
    const int rem = cnt - m0;
#pragma unroll
    for (int i = 0; i < 4; i++) {
        int m = ty * 4 + i;
        if (m < rem) {
            size_t s = (size_t)(start + m0 + m);
            float h[4];
#pragma unroll
            for (int j = 0; j < 4; j++) {
                float g  = fminf(accG[i][j], 10.f);
                float u  = fminf(fmaxf(accU[i][j], -10.f), 10.f);
                float sg = 1.f / (1.f + __expf(-g));   // silu(g) = g*sigmoid(g); overflow -> 0, correct limit
                h[j] = g * sg * u;
            }
            *(float4*)&g_hbuf[s * DIM_N + n0 + tx * 4] = make_float4(h[0], h[1], h[2], h[3]);
        }
    }
}

// ---------------------------------------------------------------------------
// Kernel 4: down GEMM + gate-weighted combine.
//   d[c][k] = sum_n h[c][n] * down_w[e][k][n];  out[token] += gate * d
// Exactly 2 atomicAdds per output element (TOPK=2) -> bitwise deterministic.
// ---------------------------------------------------------------------------
__global__ __launch_bounds__(256)
void gemm2_combine_kernel(const float* __restrict__ down_w,
                          const float* __restrict__ flat_gate,
                          float* __restrict__ out) {
    const int e   = blockIdx.z;
    const int cnt = g_counts[e];
    const int m0  = blockIdx.y * BM;
    if (m0 >= cnt) return;
    const int k0out = blockIdx.x * BN;
    const int start = g_starts[e];

    const int tid = threadIdx.x;
    const int tx  = tid & 15;
    const int ty  = tid >> 4;
    const int lr  = tid >> 2;
    const int lq  = tid & 3;

    __shared__ float As[BK][BM];
    __shared__ float Bs[BK][BN];
    __shared__ int   sh_tok[BM];
    __shared__ float sh_gate[BM];

    if (tid < BM) {
        int m = m0 + tid;
        if (m < cnt) {
            int r = g_sorted_row[start + m];
            sh_tok[tid]  = r >> 1;
            sh_gate[tid] = flat_gate[r];
        } else {
            sh_tok[tid]  = -1;
            sh_gate[tid] = 0.f;
        }
    }
    __syncthreads();

    const bool avalid = (m0 + lr) < cnt;
    const size_t srow = avalid ? (size_t)(start + m0 + lr) : 0;
    const float* aptr = g_hbuf + srow * DIM_N + lq * 4;
    const float* bptr = down_w + ((size_t)e * DIM_K + k0out + lr) * DIM_N + lq * 4;

    float acc[4][4];
#pragma unroll
    for (int i = 0; i < 4; i++)
#pragma unroll
        for (int j = 0; j < 4; j++) acc[i][j] = 0.f;

    for (int n0 = 0; n0 < DIM_N; n0 += BK) {
        float4 av = avalid ? *(const float4*)(aptr + n0) : make_float4(0.f, 0.f, 0.f, 0.f);
        float4 bv = *(const float4*)(bptr + n0);
        const int kk = lq * 4;
        As[kk + 0][lr] = av.x; As[kk + 1][lr] = av.y; As[kk + 2][lr] = av.z; As[kk + 3][lr] = av.w;
        Bs[kk + 0][lr] = bv.x; Bs[kk + 1][lr] = bv.y; Bs[kk + 2][lr] = bv.z; Bs[kk + 3][lr] = bv.w;
        __syncthreads();

#pragma unroll
        for (int k = 0; k < BK; k++) {
            float4 a4 = *(const float4*)&As[k][ty * 4];
            float4 b4 = *(const float4*)&Bs[k][tx * 4];
            float rA[4] = {a4.x, a4.y, a4.z, a4.w};
            float rB[4] = {b4.x, b4.y, b4.z, b4.w};
#pragma unroll
            for (int i = 0; i < 4; i++)
#pragma unroll
                for (int j = 0; j < 4; j++) acc[i][j] += rA[i] * rB[j];
        }
        __syncthreads();
    }

    const int rem = cnt - m0;
#pragma unroll
    for (int i = 0; i < 4; i++) {
        int m = ty * 4 + i;
        if (m < rem) {
            int   tok = sh_tok[m];
            float gt  = sh_gate[m];
            float* op = out + (size_t)tok * DIM_K + k0out + tx * 4;
#pragma unroll
            for (int j = 0; j < 4; j++) atomicAdd(op + j, gt * acc[i][j]);
        }
    }
}

// ---------------------------------------------------------------------------
// kernel_launch — graph-capturable: kernels only, no syncs/allocs.
// Inputs (metadata order): flat_h, flat_idx, flat_gate, gate_weight, up_weight, down_weight
// ---------------------------------------------------------------------------
extern "C" void kernel_launch(void* const* d_in, const int* in_sizes, int n_in,
                              void* d_out, int out_size) {
    const float* flat_h    = (const float*)d_in[0];
    const int*   flat_idx  = (const int*)  d_in[1];
    const float* flat_gate = (const float*)d_in[2];
    const float* gate_w    = (const float*)d_in[3];
    const float* up_w      = (const float*)d_in[4];
    const float* down_w    = (const float*)d_in[5];
    float*       out       = (float*)d_out;

    route_kernel<<<1, 256>>>(flat_idx);

    const int n4 = (TOK_M * DIM_K) / 4;
    zero_kernel<<<(n4 + 255) / 256, 256>>>((float4*)out, n4);

    dim3 g1(DIM_N / BN, NROWS / BM, NEXP);   // (22, 64, 8) — m-tiles beyond count exit fast
    gemm1_swiglu_kernel<<<g1, 256>>>(flat_h, gate_w, up_w);

    dim3 g2(DIM_K / BN, NROWS / BM, NEXP);   // (32, 64, 8)
    gemm2_combine_kernel<<<g2, 256>>>(down_w, flat_gate, out);
}

// round 12
// speedup vs baseline: 3.0172x; 3.0172x over previous
#include <cuda_runtime.h>
#include <cuda_bf16.h>
#include <stdint.h>
#include <math.h>

// ---------------------------------------------------------------------------
// Problem constants
// ---------------------------------------------------------------------------
#define TOK_M 2048
#define DIM_K 2048
#define DIM_N 1408
#define NEXP  8
#define NROWS 4096              // TOK_M * TOPK
#define BM    128               // CTA M tile
#define BK    32                // K chunk (bf16)
#define NCH1  (DIM_K/BK)        // 64
#define NCH2  (DIM_N/BK)        // 44
#define MT    (NROWS/BM)        // 32 max m-tiles

// ---------------------------------------------------------------------------
// Device scratch (static; no allocations anywhere)
// ---------------------------------------------------------------------------
__device__ int g_sorted_row[NROWS];
__device__ int g_counts[NEXP];
__device__ int g_starts[NEXP];

__device__ __nv_bfloat16 g_Ahi[(size_t)TOK_M * DIM_K];
__device__ __nv_bfloat16 g_Alo[(size_t)TOK_M * DIM_K];
__device__ __nv_bfloat16 g_GWhi[(size_t)NEXP * DIM_N * DIM_K];
__device__ __nv_bfloat16 g_GWlo[(size_t)NEXP * DIM_N * DIM_K];
__device__ __nv_bfloat16 g_UWhi[(size_t)NEXP * DIM_N * DIM_K];
__device__ __nv_bfloat16 g_UWlo[(size_t)NEXP * DIM_N * DIM_K];
__device__ __nv_bfloat16 g_DWhi[(size_t)NEXP * DIM_K * DIM_N];
__device__ __nv_bfloat16 g_DWlo[(size_t)NEXP * DIM_K * DIM_N];
__device__ __nv_bfloat16 g_Hhi[(size_t)NROWS * DIM_N];
__device__ __nv_bfloat16 g_Hlo[(size_t)NROWS * DIM_N];

// ---------------------------------------------------------------------------
// Helpers (all base-target instructions: sm_80/sm_90 era, NO 'a' features)
// ---------------------------------------------------------------------------
__device__ __forceinline__ uint32_t smem_u32(const void* p) {
    uint32_t a;
    asm("{ .reg .u64 t; cvta.to.shared.u64 t, %1; cvt.u32.u64 %0, t; }" : "=r"(a) : "l"(p));
    return a;
}
__device__ __forceinline__ void cp16(uint32_t dst, const void* src, uint32_t sz) {
    asm volatile("cp.async.cg.shared.global [%0], [%1], 16, %2;"
                 :: "r"(dst), "l"(src), "r"(sz) : "memory");
}
#define CP_COMMIT() asm volatile("cp.async.commit_group;" ::: "memory")
#define CP_WAIT1()  asm volatile("cp.async.wait_group 1;" ::: "memory")
#define CP_WAIT0()  asm volatile("cp.async.wait_group 0;" ::: "memory")

__device__ __forceinline__ void ldsm4(uint32_t (&r)[4], uint32_t a) {
    asm volatile("ldmatrix.sync.aligned.m8n8.x4.shared.b16 {%0,%1,%2,%3}, [%4];"
                 : "=r"(r[0]), "=r"(r[1]), "=r"(r[2]), "=r"(r[3]) : "r"(a));
}
__device__ __forceinline__ void mma16816(float (&c)[4], const uint32_t (&a)[4],
                                         uint32_t b0, uint32_t b1) {
    asm volatile(
        "mma.sync.aligned.m16n8k16.row.col.f32.bf16.bf16.f32 "
        "{%0,%1,%2,%3}, {%4,%5,%6,%7}, {%8,%9}, {%0,%1,%2,%3};"
        : "+f"(c[0]), "+f"(c[1]), "+f"(c[2]), "+f"(c[3])
        : "r"(a[0]), "r"(a[1]), "r"(a[2]), "r"(a[3]), "r"(b0), "r"(b1));
}

// SMEM tile layout: row-major [rows][BK], 64B/row, XOR swizzle on 16B chunks.
// Conflict-free for both cp.async STS and ldmatrix (8 distinct bank groups).
#define SMOFF(row, c4) ((uint32_t)((row) * 64 + (((c4) ^ (((row) >> 1) & 3)) << 4)))

// ---------------------------------------------------------------------------
// Routing: stable counting sort by expert (1 block, 256 threads)
// ---------------------------------------------------------------------------
__global__ void route_kernel(const int* __restrict__ flat_idx) {
    __shared__ int sh_cnt[256][NEXP];
    __shared__ int sh_tot[NEXP];
    __shared__ int sh_start[NEXP];
    const int t = threadIdx.x, per = NROWS / 256, base = t * per;
    int local[NEXP];
#pragma unroll
    for (int e = 0; e < NEXP; e++) local[e] = 0;
    for (int i = 0; i < per; i++) local[flat_idx[base + i]]++;
#pragma unroll
    for (int e = 0; e < NEXP; e++) sh_cnt[t][e] = local[e];
    __syncthreads();
    if (t < NEXP) {
        int run = 0;
        for (int u = 0; u < 256; u++) { int v = sh_cnt[u][t]; sh_cnt[u][t] = run; run += v; }
        sh_tot[t] = run;
    }
    __syncthreads();
    if (t == 0) {
        int run = 0;
        for (int e = 0; e < NEXP; e++) {
            sh_start[e] = run; g_starts[e] = run; g_counts[e] = sh_tot[e]; run += sh_tot[e];
        }
    }
    __syncthreads();
    int off[NEXP];
#pragma unroll
    for (int e = 0; e < NEXP; e++) off[e] = sh_start[e] + sh_cnt[t][e];
    for (int i = 0; i < per; i++) {
        int e = flat_idx[base + i];
        g_sorted_row[off[e]++] = base + i;
    }
}

// ---------------------------------------------------------------------------
// fp32 -> (bf16 hi, bf16 lo) split conversion
// ---------------------------------------------------------------------------
__global__ void cvt_kernel(const float4* __restrict__ src,
                           uint2* __restrict__ hi, uint2* __restrict__ lo, int n4) {
    for (int i = blockIdx.x * blockDim.x + threadIdx.x; i < n4; i += gridDim.x * blockDim.x) {
        float4 f = src[i];
        __nv_bfloat16 h0 = __float2bfloat16(f.x), h1 = __float2bfloat16(f.y);
        __nv_bfloat16 h2 = __float2bfloat16(f.z), h3 = __float2bfloat16(f.w);
        __nv_bfloat16 l0 = __float2bfloat16(f.x - __bfloat162float(h0));
        __nv_bfloat16 l1 = __float2bfloat16(f.y - __bfloat162float(h1));
        __nv_bfloat16 l2 = __float2bfloat16(f.z - __bfloat162float(h2));
        __nv_bfloat16 l3 = __float2bfloat16(f.w - __bfloat162float(h3));
        uint2 H, L;
        H.x = (uint32_t)__bfloat16_as_ushort(h0) | ((uint32_t)__bfloat16_as_ushort(h1) << 16);
        H.y = (uint32_t)__bfloat16_as_ushort(h2) | ((uint32_t)__bfloat16_as_ushort(h3) << 16);
        L.x = (uint32_t)__bfloat16_as_ushort(l0) | ((uint32_t)__bfloat16_as_ushort(l1) << 16);
        L.y = (uint32_t)__bfloat16_as_ushort(l2) | ((uint32_t)__bfloat16_as_ushort(l3) << 16);
        hi[i] = H; lo[i] = L;
    }
}

__global__ void zero_kernel(float4* __restrict__ p, int n4) {
    int i = blockIdx.x * blockDim.x + threadIdx.x;
    if (i < n4) p[i] = make_float4(0.f, 0.f, 0.f, 0.f);
}

// ---------------------------------------------------------------------------
// GEMM1: fused gate+up mma.sync GEMM + SwiGLU epilogue -> split-bf16 H
// CTA tile 128(M) x 64(N) x 32(K). 8 warps (4x2), warp tile 32x32 per matrix.
// SMEM/stage: Ahi Alo (8KB each), Ggate hi/lo, Gup hi/lo (4KB each) = 32KB; x2 stages.
// ---------------------------------------------------------------------------
#define G1_STAGE 32768
#define O_AH 0
#define O_AL 8192
#define O_GH 16384
#define O_GL 20480
#define O_UH 24576
#define O_UL 28672

__global__ __launch_bounds__(256, 2)
void gemm1_kernel() {
    const int e   = blockIdx.z;
    const int cnt = g_counts[e];
    const int m0  = blockIdx.y * BM;
    if (m0 >= cnt) return;
    const int n0    = blockIdx.x * 64;
    const int start = g_starts[e];
    const int tid   = threadIdx.x;
    const int lane  = tid & 31, wid = tid >> 5;
    const int wm = wid & 3, wn = wid >> 2;

    extern __shared__ char smem[];
    const uint32_t sb = smem_u32(smem);

    __shared__ int sh_tok[BM];
    if (tid < BM) {
        int m = m0 + tid;
        sh_tok[tid] = (m < cnt) ? (g_sorted_row[start + m] >> 1) : -1;
    }
    __syncthreads();

    // ---- global->smem geometry
    uint32_t a_sm[2], a_sz[2];
    size_t   a_go[2];
#pragma unroll
    for (int i = 0; i < 2; i++) {
        int idx = tid + i * 256;
        int row = idx >> 2, c4 = idx & 3;
        a_sm[i] = SMOFF(row, c4);
        int tok = sh_tok[row];
        a_sz[i] = (tok >= 0) ? 16u : 0u;
        a_go[i] = (size_t)(tok >= 0 ? tok : 0) * DIM_K + c4 * 8;
    }
    const int brow = tid >> 2, bc4 = tid & 3;              // B rows 0..63
    const uint32_t b_sm = SMOFF(brow, bc4);
    const size_t   b_go = ((size_t)e * DIM_N + n0 + brow) * DIM_K + bc4 * 8;

    // ---- ldmatrix offsets
    uint32_t offA[2][2], offB[2][2];
#pragma unroll
    for (int mf = 0; mf < 2; mf++)
#pragma unroll
        for (int ks = 0; ks < 2; ks++) {
            int row = wm * 32 + mf * 16 + (lane & 15);
            int c4  = ks * 2 + (lane >> 4);
            offA[mf][ks] = SMOFF(row, c4);
        }
#pragma unroll
    for (int p = 0; p < 2; p++)
#pragma unroll
        for (int ks = 0; ks < 2; ks++) {
            int row = wn * 32 + p * 16 + ((lane >> 4) & 1) * 8 + (lane & 7);
            int c4  = ks * 2 + ((lane >> 3) & 1);
            offB[p][ks] = SMOFF(row, c4);
        }

    float accG[2][4][4], accU[2][4][4];
#pragma unroll
    for (int mf = 0; mf < 2; mf++)
#pragma unroll
        for (int nf = 0; nf < 4; nf++)
#pragma unroll
            for (int q = 0; q < 4; q++) { accG[mf][nf][q] = 0.f; accU[mf][nf][q] = 0.f; }

    // prologue: stage 0
    {
#pragma unroll
        for (int i = 0; i < 2; i++) {
            cp16(sb + O_AH + a_sm[i], g_Ahi + a_go[i], a_sz[i]);
            cp16(sb + O_AL + a_sm[i], g_Alo + a_go[i], a_sz[i]);
        }
        cp16(sb + O_GH + b_sm, g_GWhi + b_go, 16u);
        cp16(sb + O_GL + b_sm, g_GWlo + b_go, 16u);
        cp16(sb + O_UH + b_sm, g_UWhi + b_go, 16u);
        cp16(sb + O_UL + b_sm, g_UWlo + b_go, 16u);
        CP_COMMIT();
    }

    for (int c = 0; c < NCH1; c++) {
        const uint32_t base = sb + (uint32_t)(c & 1) * G1_STAGE;
        if (c + 1 < NCH1) {
            const uint32_t nb = sb + (uint32_t)((c + 1) & 1) * G1_STAGE;
            const int k0 = (c + 1) * BK;
#pragma unroll
            for (int i = 0; i < 2; i++) {
                cp16(nb + O_AH + a_sm[i], g_Ahi + a_go[i] + k0, a_sz[i]);
                cp16(nb + O_AL + a_sm[i], g_Alo + a_go[i] + k0, a_sz[i]);
            }
            cp16(nb + O_GH + b_sm, g_GWhi + b_go + k0, 16u);
            cp16(nb + O_GL + b_sm, g_GWlo + b_go + k0, 16u);
            cp16(nb + O_UH + b_sm, g_UWhi + b_go + k0, 16u);
            cp16(nb + O_UL + b_sm, g_UWlo + b_go + k0, 16u);
            CP_COMMIT();
            CP_WAIT1();
        } else {
            CP_WAIT0();
        }
        __syncthreads();

#pragma unroll
        for (int ks = 0; ks < 2; ks++) {
            uint32_t ah[2][4], al[2][4];
            ldsm4(ah[0], base + O_AH + offA[0][ks]);
            ldsm4(ah[1], base + O_AH + offA[1][ks]);
            ldsm4(al[0], base + O_AL + offA[0][ks]);
            ldsm4(al[1], base + O_AL + offA[1][ks]);
            uint32_t gh[2][4], gl[2][4], uh[2][4], ul[2][4];
#pragma unroll
            for (int p = 0; p < 2; p++) {
                ldsm4(gh[p], base + O_GH + offB[p][ks]);
                ldsm4(gl[p], base + O_GL + offB[p][ks]);
                ldsm4(uh[p], base + O_UH + offB[p][ks]);
                ldsm4(ul[p], base + O_UL + offB[p][ks]);
            }
#pragma unroll
            for (int mf = 0; mf < 2; mf++)
#pragma unroll
                for (int nf = 0; nf < 4; nf++) {
                    const int p = nf >> 1, q = (nf & 1) * 2;
                    mma16816(accG[mf][nf], ah[mf], gh[p][q], gh[p][q + 1]);
                    mma16816(accG[mf][nf], ah[mf], gl[p][q], gl[p][q + 1]);
                    mma16816(accG[mf][nf], al[mf], gh[p][q], gh[p][q + 1]);
                    mma16816(accU[mf][nf], ah[mf], uh[p][q], uh[p][q + 1]);
                    mma16816(accU[mf][nf], ah[mf], ul[p][q], ul[p][q + 1]);
                    mma16816(accU[mf][nf], al[mf], uh[p][q], uh[p][q + 1]);
                }
        }
        __syncthreads();
    }

    // SwiGLU epilogue -> split-bf16 H
    const int rem = cnt - m0;
#pragma unroll
    for (int mf = 0; mf < 2; mf++)
#pragma unroll
        for (int half = 0; half < 2; half++) {
            int r = wm * 32 + mf * 16 + (lane >> 2) + half * 8;
            if (r < rem) {
                size_t s = (size_t)(start + m0 + r);
#pragma unroll
                for (int nf = 0; nf < 4; nf++) {
                    float g0 = fminf(accG[mf][nf][half * 2 + 0], 10.f);
                    float g1 = fminf(accG[mf][nf][half * 2 + 1], 10.f);
                    float u0 = fminf(fmaxf(accU[mf][nf][half * 2 + 0], -10.f), 10.f);
                    float u1 = fminf(fmaxf(accU[mf][nf][half * 2 + 1], -10.f), 10.f);
                    float h0 = g0 / (1.f + __expf(-g0)) * u0;
                    float h1 = g1 / (1.f + __expf(-g1)) * u1;
                    __nv_bfloat16 a0 = __float2bfloat16(h0), a1 = __float2bfloat16(h1);
                    __nv_bfloat16 b0 = __float2bfloat16(h0 - __bfloat162float(a0));
                    __nv_bfloat16 b1 = __float2bfloat16(h1 - __bfloat162float(a1));
                    int col = n0 + wn * 32 + nf * 8 + (lane & 3) * 2;
                    uint32_t hv = (uint32_t)__bfloat16_as_ushort(a0) | ((uint32_t)__bfloat16_as_ushort(a1) << 16);
                    uint32_t lv = (uint32_t)__bfloat16_as_ushort(b0) | ((uint32_t)__bfloat16_as_ushort(b1) << 16);
                    *(uint32_t*)(g_Hhi + s * DIM_N + col) = hv;
                    *(uint32_t*)(g_Hlo + s * DIM_N + col) = lv;
                }
            }
        }
}

// ---------------------------------------------------------------------------
// GEMM2: down GEMM (mma.sync split-bf16) + fused gate-weighted vector-red combine
// CTA tile 128(M) x 128(Nout) x 32(K=DIM_N). 8 warps (4x2), warp tile 32x64.
// SMEM/stage: Ahi Alo Bh Bl = 8KB each = 32KB; x2 stages.
// ---------------------------------------------------------------------------
#define O2_AH 0
#define O2_AL 8192
#define O2_BH 16384
#define O2_BL 24576

__global__ __launch_bounds__(256, 2)
void gemm2_kernel(const float* __restrict__ flat_gate, float* __restrict__ out) {
    const int e   = blockIdx.z;
    const int cnt = g_counts[e];
    const int m0  = blockIdx.y * BM;
    if (m0 >= cnt) return;
    const int k0out = blockIdx.x * 128;
    const int start = g_starts[e];
    const int tid   = threadIdx.x;
    const int lane  = tid & 31, wid = tid >> 5;
    const int wm = wid & 3, wn = wid >> 2;
    const int rem = cnt - m0;

    extern __shared__ char smem[];
    const uint32_t sb = smem_u32(smem);

    __shared__ int   sh_tok[BM];
    __shared__ float sh_gate[BM];
    if (tid < BM) {
        int m = m0 + tid;
        if (m < cnt) {
            int r = g_sorted_row[start + m];
            sh_tok[tid] = r >> 1; sh_gate[tid] = flat_gate[r];
        } else { sh_tok[tid] = 0; sh_gate[tid] = 0.f; }
    }
    __syncthreads();

    uint32_t a_sm[2], a_sz[2], b_sm[2];
    size_t   a_go[2], b_go[2];
#pragma unroll
    for (int i = 0; i < 2; i++) {
        int idx = tid + i * 256;
        int row = idx >> 2, c4 = idx & 3;
        a_sm[i] = SMOFF(row, c4);
        b_sm[i] = a_sm[i];
        bool v  = (row < rem);
        a_sz[i] = v ? 16u : 0u;
        a_go[i] = (size_t)(start + m0 + (v ? row : 0)) * DIM_N + c4 * 8;
        b_go[i] = ((size_t)e * DIM_K + k0out + row) * DIM_N + c4 * 8;
    }

    uint32_t offA[2][2], offB[4][2];
#pragma unroll
    for (int mf = 0; mf < 2; mf++)
#pragma unroll
        for (int ks = 0; ks < 2; ks++) {
            int row = wm * 32 + mf * 16 + (lane & 15);
            int c4  = ks * 2 + (lane >> 4);
            offA[mf][ks] = SMOFF(row, c4);
        }
#pragma unroll
    for (int p = 0; p < 4; p++)
#pragma unroll
        for (int ks = 0; ks < 2; ks++) {
            int row = wn * 64 + p * 16 + ((lane >> 4) & 1) * 8 + (lane & 7);
            int c4  = ks * 2 + ((lane >> 3) & 1);
            offB[p][ks] = SMOFF(row, c4);
        }

    float acc[2][8][4];
#pragma unroll
    for (int mf = 0; mf < 2; mf++)
#pragma unroll
        for (int nf = 0; nf < 8; nf++)
#pragma unroll
            for (int q = 0; q < 4; q++) acc[mf][nf][q] = 0.f;

    {
#pragma unroll
        for (int i = 0; i < 2; i++) {
            cp16(sb + O2_AH + a_sm[i], g_Hhi + a_go[i], a_sz[i]);
            cp16(sb + O2_AL + a_sm[i], g_Hlo + a_go[i], a_sz[i]);
            cp16(sb + O2_BH + b_sm[i], g_DWhi + b_go[i], 16u);
            cp16(sb + O2_BL + b_sm[i], g_DWlo + b_go[i], 16u);
        }
        CP_COMMIT();
    }

    for (int c = 0; c < NCH2; c++) {
        const uint32_t base = sb + (uint32_t)(c & 1) * G1_STAGE;
        if (c + 1 < NCH2) {
            const uint32_t nb = sb + (uint32_t)((c + 1) & 1) * G1_STAGE;
            const int k0 = (c + 1) * BK;
#pragma unroll
            for (int i = 0; i < 2; i++) {
                cp16(nb + O2_AH + a_sm[i], g_Hhi + a_go[i] + k0, a_sz[i]);
                cp16(nb + O2_AL + a_sm[i], g_Hlo + a_go[i] + k0, a_sz[i]);
                cp16(nb + O2_BH + b_sm[i], g_DWhi + b_go[i] + k0, 16u);
                cp16(nb + O2_BL + b_sm[i], g_DWlo + b_go[i] + k0, 16u);
            }
            CP_COMMIT();
            CP_WAIT1();
        } else {
            CP_WAIT0();
        }
        __syncthreads();

#pragma unroll
        for (int ks = 0; ks < 2; ks++) {
            uint32_t ah[2][4], al[2][4];
            ldsm4(ah[0], base + O2_AH + offA[0][ks]);
            ldsm4(ah[1], base + O2_AH + offA[1][ks]);
            ldsm4(al[0], base + O2_AL + offA[0][ks]);
            ldsm4(al[1], base + O2_AL + offA[1][ks]);
            uint32_t bh[4][4], bl[4][4];
#pragma unroll
            for (int p = 0; p < 4; p++) {
                ldsm4(bh[p], base + O2_BH + offB[p][ks]);
                ldsm4(bl[p], base + O2_BL + offB[p][ks]);
            }
#pragma unroll
            for (int mf = 0; mf < 2; mf++)
#pragma unroll
                for (int nf = 0; nf < 8; nf++) {
                    const int p = nf >> 1, q = (nf & 1) * 2;
                    mma16816(acc[mf][nf], ah[mf], bh[p][q], bh[p][q + 1]);
                    mma16816(acc[mf][nf], ah[mf], bl[p][q], bl[p][q + 1]);
                    mma16816(acc[mf][nf], al[mf], bh[p][q], bh[p][q + 1]);
                }
        }
        __syncthreads();
    }

    // Gate-weighted combine via vector reduction (no return) — 2 fp32 per red
#pragma unroll
    for (int mf = 0; mf < 2; mf++)
#pragma unroll
        for (int half = 0; half < 2; half++) {
            int r = wm * 32 + mf * 16 + (lane >> 2) + half * 8;
            if (r < rem) {
                const int   tok = sh_tok[r];
                const float gt  = sh_gate[r];
                float* orow = out + (size_t)tok * DIM_K;
#pragma unroll
                for (int nf = 0; nf < 8; nf++) {
                    int col = k0out + wn * 64 + nf * 8 + (lane & 3) * 2;
                    float v0 = gt * acc[mf][nf][half * 2 + 0];
                    float v1 = gt * acc[mf][nf][half * 2 + 1];
                    asm volatile("red.global.add.v2.f32 [%0], {%1, %2};"
                                 :: "l"(orow + col), "f"(v0), "f"(v1) : "memory");
                }
            }
        }
}

// ---------------------------------------------------------------------------
// kernel_launch — graph-capturable (kernel launches only)
// Inputs: flat_h, flat_idx, flat_gate, gate_weight, up_weight, down_weight
// ---------------------------------------------------------------------------
extern "C" void kernel_launch(void* const* d_in, const int* in_sizes, int n_in,
                              void* d_out, int out_size) {
    const float* flat_h    = (const float*)d_in[0];
    const int*   flat_idx  = (const int*)  d_in[1];
    const float* flat_gate = (const float*)d_in[2];
    const float* gate_w    = (const float*)d_in[3];
    const float* up_w      = (const float*)d_in[4];
    const float* down_w    = (const float*)d_in[5];
    float*       out       = (float*)d_out;

    cudaFuncSetAttribute(gemm1_kernel, cudaFuncAttributeMaxDynamicSharedMemorySize, 2 * G1_STAGE);
    cudaFuncSetAttribute(gemm2_kernel, cudaFuncAttributeMaxDynamicSharedMemorySize, 2 * G1_STAGE);

    route_kernel<<<1, 256>>>(flat_idx);

    __nv_bfloat16 *Ahi, *Alo, *GWhi, *GWlo, *UWhi, *UWlo, *DWhi, *DWlo;
    cudaGetSymbolAddress((void**)&Ahi,  g_Ahi);  cudaGetSymbolAddress((void**)&Alo,  g_Alo);
    cudaGetSymbolAddress((void**)&GWhi, g_GWhi); cudaGetSymbolAddress((void**)&GWlo, g_GWlo);
    cudaGetSymbolAddress((void**)&UWhi, g_UWhi); cudaGetSymbolAddress((void**)&UWlo, g_UWlo);
    cudaGetSymbolAddress((void**)&DWhi, g_DWhi); cudaGetSymbolAddress((void**)&DWlo, g_DWlo);

    const int nA4 = (TOK_M * DIM_K) / 4;
    const int nW4 = (NEXP * DIM_N * DIM_K) / 4;
    cvt_kernel<<<2048, 256>>>((const float4*)flat_h, (uint2*)Ahi,  (uint2*)Alo,  nA4);
    cvt_kernel<<<8192, 256>>>((const float4*)gate_w, (uint2*)GWhi, (uint2*)GWlo, nW4);
    cvt_kernel<<<8192, 256>>>((const float4*)up_w,   (uint2*)UWhi, (uint2*)UWlo, nW4);
    cvt_kernel<<<8192, 256>>>((const float4*)down_w, (uint2*)DWhi, (uint2*)DWlo, nW4);

    const int n4 = (TOK_M * DIM_K) / 4;
    zero_kernel<<<(n4 + 255) / 256, 256>>>((float4*)out, n4);

    dim3 g1(DIM_N / 64, MT, NEXP);    // (22, 32, 8)
    gemm1_kernel<<<g1, 256, 2 * G1_STAGE>>>();

    dim3 g2(DIM_K / 128, MT, NEXP);   // (16, 32, 8)
    gemm2_kernel<<<g2, 256, 2 * G1_STAGE>>>(flat_gate, out);
}

// round 15
// speedup vs baseline: 3.1345x; 1.0389x over previous
#include <cuda_runtime.h>
#include <cuda_bf16.h>
#include <stdint.h>
#include <math.h>

// ---------------------------------------------------------------------------
// Problem constants
// ---------------------------------------------------------------------------
#define TOK_M 2048
#define DIM_K 2048
#define DIM_N 1408
#define NEXP  8
#define NROWS 4096              // TOK_M * TOPK
#define BM    128               // CTA M tile
#define BK    32                // K chunk (bf16)
#define NCH1  (DIM_K/BK)        // 64
#define NCH2  (DIM_N/BK)        // 44
#define MT    8                 // m-tiles per expert (capacity 1024 = reference CAPACITY)

// ---------------------------------------------------------------------------
// Device scratch (static; no allocations anywhere)
// ---------------------------------------------------------------------------
__device__ int g_sorted_row[NROWS];
__device__ int g_counts[NEXP];
__device__ int g_starts[NEXP];

__device__ __nv_bfloat16 g_Ahi[(size_t)TOK_M * DIM_K];
__device__ __nv_bfloat16 g_Alo[(size_t)TOK_M * DIM_K];
__device__ __nv_bfloat16 g_GWhi[(size_t)NEXP * DIM_N * DIM_K];
__device__ __nv_bfloat16 g_GWlo[(size_t)NEXP * DIM_N * DIM_K];
__device__ __nv_bfloat16 g_UWhi[(size_t)NEXP * DIM_N * DIM_K];
__device__ __nv_bfloat16 g_UWlo[(size_t)NEXP * DIM_N * DIM_K];
__device__ __nv_bfloat16 g_DWhi[(size_t)NEXP * DIM_K * DIM_N];
__device__ __nv_bfloat16 g_DWlo[(size_t)NEXP * DIM_K * DIM_N];
__device__ __nv_bfloat16 g_Hhi[(size_t)NROWS * DIM_N];
__device__ __nv_bfloat16 g_Hlo[(size_t)NROWS * DIM_N];

// ---------------------------------------------------------------------------
// Helpers (base-target instructions only: no sm_103a-gated features)
// ---------------------------------------------------------------------------
__device__ __forceinline__ uint32_t smem_u32(const void* p) {
    uint32_t a;
    asm("{ .reg .u64 t; cvta.to.shared.u64 t, %1; cvt.u32.u64 %0, t; }" : "=r"(a) : "l"(p));
    return a;
}
__device__ __forceinline__ void cp16(uint32_t dst, const void* src, uint32_t sz) {
    asm volatile("cp.async.cg.shared.global [%0], [%1], 16, %2;"
                 :: "r"(dst), "l"(src), "r"(sz) : "memory");
}
#define CP_COMMIT() asm volatile("cp.async.commit_group;" ::: "memory")
#define CP_WAIT1()  asm volatile("cp.async.wait_group 1;" ::: "memory")
#define CP_WAIT0()  asm volatile("cp.async.wait_group 0;" ::: "memory")

__device__ __forceinline__ void ldsm4(uint32_t (&r)[4], uint32_t a) {
    asm volatile("ldmatrix.sync.aligned.m8n8.x4.shared.b16 {%0,%1,%2,%3}, [%4];"
                 : "=r"(r[0]), "=r"(r[1]), "=r"(r[2]), "=r"(r[3]) : "r"(a));
}
__device__ __forceinline__ void mma16816(float (&c)[4], const uint32_t (&a)[4],
                                         uint32_t b0, uint32_t b1) {
    asm volatile(
        "mma.sync.aligned.m16n8k16.row.col.f32.bf16.bf16.f32 "
        "{%0,%1,%2,%3}, {%4,%5,%6,%7}, {%8,%9}, {%0,%1,%2,%3};"
        : "+f"(c[0]), "+f"(c[1]), "+f"(c[2]), "+f"(c[3])
        : "r"(a[0]), "r"(a[1]), "r"(a[2]), "r"(a[3]), "r"(b0), "r"(b1));
}

// SMEM tile layout: row-major [rows][BK], 64B/row, XOR swizzle on 16B chunks.
#define SMOFF(row, c4) ((uint32_t)((row) * 64 + (((c4) ^ (((row) >> 1) & 3)) << 4)))

// ---------------------------------------------------------------------------
// Routing: stable counting sort by expert (1 block, 256 threads)
// ---------------------------------------------------------------------------
__global__ void route_kernel(const int* __restrict__ flat_idx) {
    __shared__ int sh_cnt[256][NEXP];
    __shared__ int sh_tot[NEXP];
    __shared__ int sh_start[NEXP];
    const int t = threadIdx.x, per = NROWS / 256, base = t * per;
    int local[NEXP];
#pragma unroll
    for (int e = 0; e < NEXP; e++) local[e] = 0;
    for (int i = 0; i < per; i++) local[flat_idx[base + i]]++;
#pragma unroll
    for (int e = 0; e < NEXP; e++) sh_cnt[t][e] = local[e];
    __syncthreads();
    if (t < NEXP) {
        int run = 0;
        for (int u = 0; u < 256; u++) { int v = sh_cnt[u][t]; sh_cnt[u][t] = run; run += v; }
        sh_tot[t] = run;
    }
    __syncthreads();
    if (t == 0) {
        int run = 0;
        for (int e = 0; e < NEXP; e++) {
            sh_start[e] = run; g_starts[e] = run; g_counts[e] = sh_tot[e]; run += sh_tot[e];
        }
    }
    __syncthreads();
    int off[NEXP];
#pragma unroll
    for (int e = 0; e < NEXP; e++) off[e] = sh_start[e] + sh_cnt[t][e];
    for (int i = 0; i < per; i++) {
        int e = flat_idx[base + i];
        g_sorted_row[off[e]++] = base + i;
    }
}

// ---------------------------------------------------------------------------
// fp32 -> (bf16 hi, bf16 lo) split conversion; 8 elems/thread, streaming hints
// ---------------------------------------------------------------------------
__global__ void cvt_kernel(const float4* __restrict__ src,
                           uint4* __restrict__ hi, uint4* __restrict__ lo, int n8) {
    for (int i = blockIdx.x * blockDim.x + threadIdx.x; i < n8; i += gridDim.x * blockDim.x) {
        float4 f0 = __ldcs(src + 2 * i);
        float4 f1 = __ldcs(src + 2 * i + 1);
        float v[8] = {f0.x, f0.y, f0.z, f0.w, f1.x, f1.y, f1.z, f1.w};
        uint32_t hw[4], lw[4];
#pragma unroll
        for (int p = 0; p < 4; p++) {
            __nv_bfloat16 h0 = __float2bfloat16(v[2 * p]);
            __nv_bfloat16 h1 = __float2bfloat16(v[2 * p + 1]);
            __nv_bfloat16 l0 = __float2bfloat16(v[2 * p] - __bfloat162float(h0));
            __nv_bfloat16 l1 = __float2bfloat16(v[2 * p + 1] - __bfloat162float(h1));
            hw[p] = (uint32_t)__bfloat16_as_ushort(h0) | ((uint32_t)__bfloat16_as_ushort(h1) << 16);
            lw[p] = (uint32_t)__bfloat16_as_ushort(l0) | ((uint32_t)__bfloat16_as_ushort(l1) << 16);
        }
        __stcs(hi + i, make_uint4(hw[0], hw[1], hw[2], hw[3]));
        __stcs(lo + i, make_uint4(lw[0], lw[1], lw[2], lw[3]));
    }
}

__global__ void zero_kernel(float4* __restrict__ p, int n4) {
    int i = blockIdx.x * blockDim.x + threadIdx.x;
    if (i < n4) p[i] = make_float4(0.f, 0.f, 0.f, 0.f);
}

// ---------------------------------------------------------------------------
// GEMM1: fused gate+up mma.sync GEMM + SwiGLU epilogue -> split-bf16 H
// CTA tile 128(M) x 64(N) x 32(K). 8 warps (4x2), warp tile 32x32 per matrix.
// 3-stage cp.async pipeline, prefetch distance 2, one sync per chunk.
// ---------------------------------------------------------------------------
#define G1_STAGE 32768
#define O_AH 0
#define O_AL 8192
#define O_GH 16384
#define O_GL 20480
#define O_UH 24576
#define O_UL 28672

__global__ __launch_bounds__(256, 2)
void gemm1_kernel() {
    const int e   = blockIdx.z;
    const int cnt = g_counts[e];
    const int m0  = blockIdx.y * BM;
    if (m0 >= cnt) return;
    const int n0    = blockIdx.x * 64;
    const int start = g_starts[e];
    const int tid   = threadIdx.x;
    const int lane  = tid & 31, wid = tid >> 5;
    const int wm = wid & 3, wn = wid >> 2;

    extern __shared__ char smem[];
    const uint32_t sb = smem_u32(smem);

    __shared__ int sh_tok[BM];
    if (tid < BM) {
        int m = m0 + tid;
        sh_tok[tid] = (m < cnt) ? (g_sorted_row[start + m] >> 1) : -1;
    }
    __syncthreads();

    // ---- global->smem geometry
    uint32_t a_sm[2], a_sz[2];
    size_t   a_go[2];
#pragma unroll
    for (int i = 0; i < 2; i++) {
        int idx = tid + i * 256;
        int row = idx >> 2, c4 = idx & 3;
        a_sm[i] = SMOFF(row, c4);
        int tok = sh_tok[row];
        a_sz[i] = (tok >= 0) ? 16u : 0u;
        a_go[i] = (size_t)(tok >= 0 ? tok : 0) * DIM_K + c4 * 8;
    }
    const int brow = tid >> 2, bc4 = tid & 3;              // B rows 0..63
    const uint32_t b_sm = SMOFF(brow, bc4);
    const size_t   b_go = ((size_t)e * DIM_N + n0 + brow) * DIM_K + bc4 * 8;

    // ---- ldmatrix offsets
    uint32_t offA[2][2], offB[2][2];
#pragma unroll
    for (int mf = 0; mf < 2; mf++)
#pragma unroll
        for (int ks = 0; ks < 2; ks++) {
            int row = wm * 32 + mf * 16 + (lane & 15);
            int c4  = ks * 2 + (lane >> 4);
            offA[mf][ks] = SMOFF(row, c4);
        }
#pragma unroll
    for (int p = 0; p < 2; p++)
#pragma unroll
        for (int ks = 0; ks < 2; ks++) {
            int row = wn * 32 + p * 16 + ((lane >> 4) & 1) * 8 + (lane & 7);
            int c4  = ks * 2 + ((lane >> 3) & 1);
            offB[p][ks] = SMOFF(row, c4);
        }

    float accG[2][4][4], accU[2][4][4];
#pragma unroll
    for (int mf = 0; mf < 2; mf++)
#pragma unroll
        for (int nf = 0; nf < 4; nf++)
#pragma unroll
            for (int q = 0; q < 4; q++) { accG[mf][nf][q] = 0.f; accU[mf][nf][q] = 0.f; }

    // prologue: stages 0,1
#pragma unroll
    for (int pc = 0; pc < 2; pc++) {
        const uint32_t nb = sb + (uint32_t)pc * G1_STAGE;
        const int k0 = pc * BK;
#pragma unroll
        for (int i = 0; i < 2; i++) {
            cp16(nb + O_AH + a_sm[i], g_Ahi + a_go[i] + k0, a_sz[i]);
            cp16(nb + O_AL + a_sm[i], g_Alo + a_go[i] + k0, a_sz[i]);
        }
        cp16(nb + O_GH + b_sm, g_GWhi + b_go + k0, 16u);
        cp16(nb + O_GL + b_sm, g_GWlo + b_go + k0, 16u);
        cp16(nb + O_UH + b_sm, g_UWhi + b_go + k0, 16u);
        cp16(nb + O_UL + b_sm, g_UWlo + b_go + k0, 16u);
        CP_COMMIT();
    }

    int stage = 0, pstage = 2;   // stage of chunk c; stage for prefetch c+2
    for (int c = 0; c < NCH1; c++) {
        if (c == NCH1 - 1) { CP_WAIT0(); } else { CP_WAIT1(); }
        __syncthreads();
        if (c + 2 < NCH1) {
            const uint32_t nb = sb + (uint32_t)pstage * G1_STAGE;
            const int k0 = (c + 2) * BK;
#pragma unroll
            for (int i = 0; i < 2; i++) {
                cp16(nb + O_AH + a_sm[i], g_Ahi + a_go[i] + k0, a_sz[i]);
                cp16(nb + O_AL + a_sm[i], g_Alo + a_go[i] + k0, a_sz[i]);
            }
            cp16(nb + O_GH + b_sm, g_GWhi + b_go + k0, 16u);
            cp16(nb + O_GL + b_sm, g_GWlo + b_go + k0, 16u);
            cp16(nb + O_UH + b_sm, g_UWhi + b_go + k0, 16u);
            cp16(nb + O_UL + b_sm, g_UWlo + b_go + k0, 16u);
            CP_COMMIT();
        }
        const uint32_t base = sb + (uint32_t)stage * G1_STAGE;

#pragma unroll
        for (int ks = 0; ks < 2; ks++) {
            uint32_t ah[2][4], al[2][4];
            ldsm4(ah[0], base + O_AH + offA[0][ks]);
            ldsm4(ah[1], base + O_AH + offA[1][ks]);
            ldsm4(al[0], base + O_AL + offA[0][ks]);
            ldsm4(al[1], base + O_AL + offA[1][ks]);
            uint32_t gh[2][4], gl[2][4], uh[2][4], ul[2][4];
#pragma unroll
            for (int p = 0; p < 2; p++) {
                ldsm4(gh[p], base + O_GH + offB[p][ks]);
                ldsm4(gl[p], base + O_GL + offB[p][ks]);
                ldsm4(uh[p], base + O_UH + offB[p][ks]);
                ldsm4(ul[p], base + O_UL + offB[p][ks]);
            }
#pragma unroll
            for (int mf = 0; mf < 2; mf++)
#pragma unroll
                for (int nf = 0; nf < 4; nf++) {
                    const int p = nf >> 1, q = (nf & 1) * 2;
                    mma16816(accG[mf][nf], ah[mf], gh[p][q], gh[p][q + 1]);
                    mma16816(accG[mf][nf], ah[mf], gl[p][q], gl[p][q + 1]);
                    mma16816(accG[mf][nf], al[mf], gh[p][q], gh[p][q + 1]);
                    mma16816(accU[mf][nf], ah[mf], uh[p][q], uh[p][q + 1]);
                    mma16816(accU[mf][nf], ah[mf], ul[p][q], ul[p][q + 1]);
                    mma16816(accU[mf][nf], al[mf], uh[p][q], uh[p][q + 1]);
                }
        }
        stage  = (stage  == 2) ? 0 : stage  + 1;
        pstage = (pstage == 2) ? 0 : pstage + 1;
    }

    // SwiGLU epilogue -> split-bf16 H
    const int rem = cnt - m0;
#pragma unroll
    for (int mf = 0; mf < 2; mf++)
#pragma unroll
        for (int half = 0; half < 2; half++) {
            int r = wm * 32 + mf * 16 + (lane >> 2) + half * 8;
            if (r < rem) {
                size_t s = (size_t)(start + m0 + r);
#pragma unroll
                for (int nf = 0; nf < 4; nf++) {
                    float g0 = fminf(accG[mf][nf][half * 2 + 0], 10.f);
                    float g1 = fminf(accG[mf][nf][half * 2 + 1], 10.f);
                    float u0 = fminf(fmaxf(accU[mf][nf][half * 2 + 0], -10.f), 10.f);
                    float u1 = fminf(fmaxf(accU[mf][nf][half * 2 + 1], -10.f), 10.f);
                    float h0 = g0 / (1.f + __expf(-g0)) * u0;
                    float h1 = g1 / (1.f + __expf(-g1)) * u1;
                    __nv_bfloat16 a0 = __float2bfloat16(h0), a1 = __float2bfloat16(h1);
                    __nv_bfloat16 b0 = __float2bfloat16(h0 - __bfloat162float(a0));
                    __nv_bfloat16 b1 = __float2bfloat16(h1 - __bfloat162float(a1));
                    int col = n0 + wn * 32 + nf * 8 + (lane & 3) * 2;
                    uint32_t hv = (uint32_t)__bfloat16_as_ushort(a0) | ((uint32_t)__bfloat16_as_ushort(a1) << 16);
                    uint32_t lv = (uint32_t)__bfloat16_as_ushort(b0) | ((uint32_t)__bfloat16_as_ushort(b1) << 16);
                    *(uint32_t*)(g_Hhi + s * DIM_N + col) = hv;
                    *(uint32_t*)(g_Hlo + s * DIM_N + col) = lv;
                }
            }
        }
}

// ---------------------------------------------------------------------------
// GEMM2: down GEMM (mma.sync split-bf16) + fused gate-weighted vector-red combine
// CTA tile 128(M) x 128(Nout) x 32(K=DIM_N). 8 warps (4x2), warp tile 32x64.
// 3-stage pipeline, prefetch distance 2, one sync per chunk.
// ---------------------------------------------------------------------------
#define O2_AH 0
#define O2_AL 8192
#define O2_BH 16384
#define O2_BL 24576

__global__ __launch_bounds__(256, 2)
void gemm2_kernel(const float* __restrict__ flat_gate, float* __restrict__ out) {
    const int e   = blockIdx.z;
    const int cnt = g_counts[e];
    const int m0  = blockIdx.y * BM;
    if (m0 >= cnt) return;
    const int k0out = blockIdx.x * 128;
    const int start = g_starts[e];
    const int tid   = threadIdx.x;
    const int lane  = tid & 31, wid = tid >> 5;
    const int wm = wid & 3, wn = wid >> 2;
    const int rem = cnt - m0;

    extern __shared__ char smem[];
    const uint32_t sb = smem_u32(smem);

    __shared__ int   sh_tok[BM];
    __shared__ float sh_gate[BM];
    if (tid < BM) {
        int m = m0 + tid;
        if (m < cnt) {
            int r = g_sorted_row[start + m];
            sh_tok[tid] = r >> 1; sh_gate[tid] = flat_gate[r];
        } else { sh_tok[tid] = 0; sh_gate[tid] = 0.f; }
    }
    __syncthreads();

    uint32_t a_sm[2], a_sz[2];
    size_t   a_go[2], b_go[2];
#pragma unroll
    for (int i = 0; i < 2; i++) {
        int idx = tid + i * 256;
        int row = idx >> 2, c4 = idx & 3;
        a_sm[i] = SMOFF(row, c4);
        bool v  = (row < rem);
        a_sz[i] = v ? 16u : 0u;
        a_go[i] = (size_t)(start + m0 + (v ? row : 0)) * DIM_N + c4 * 8;
        b_go[i] = ((size_t)e * DIM_K + k0out + row) * DIM_N + c4 * 8;
    }

    uint32_t offA[2][2], offB[4][2];
#pragma unroll
    for (int mf = 0; mf < 2; mf++)
#pragma unroll
        for (int ks = 0; ks < 2; ks++) {
            int row = wm * 32 + mf * 16 + (lane & 15);
            int c4  = ks * 2 + (lane >> 4);
            offA[mf][ks] = SMOFF(row, c4);
        }
#pragma unroll
    for (int p = 0; p < 4; p++)
#pragma unroll
        for (int ks = 0; ks < 2; ks++) {
            int row = wn * 64 + p * 16 + ((lane >> 4) & 1) * 8 + (lane & 7);
            int c4  = ks * 2 + ((lane >> 3) & 1);
            offB[p][ks] = SMOFF(row, c4);
        }

    float acc[2][8][4];
#pragma unroll
    for (int mf = 0; mf < 2; mf++)
#pragma unroll
        for (int nf = 0; nf < 8; nf++)
#pragma unroll
            for (int q = 0; q < 4; q++) acc[mf][nf][q] = 0.f;

    // prologue: stages 0,1
#pragma unroll
    for (int pc = 0; pc < 2; pc++) {
        const uint32_t nb = sb + (uint32_t)pc * G1_STAGE;
        const int k0 = pc * BK;
#pragma unroll
        for (int i = 0; i < 2; i++) {
            cp16(nb + O2_AH + a_sm[i], g_Hhi + a_go[i] + k0, a_sz[i]);
            cp16(nb + O2_AL + a_sm[i], g_Hlo + a_go[i] + k0, a_sz[i]);
            cp16(nb + O2_BH + a_sm[i], g_DWhi + b_go[i] + k0, 16u);
            cp16(nb + O2_BL + a_sm[i], g_DWlo + b_go[i] + k0, 16u);
        }
        CP_COMMIT();
    }

    int stage = 0, pstage = 2;
    for (int c = 0; c < NCH2; c++) {
        if (c == NCH2 - 1) { CP_WAIT0(); } else { CP_WAIT1(); }
        __syncthreads();
        if (c + 2 < NCH2) {
            const uint32_t nb = sb + (uint32_t)pstage * G1_STAGE;
            const int k0 = (c + 2) * BK;
#pragma unroll
            for (int i = 0; i < 2; i++) {
                cp16(nb + O2_AH + a_sm[i], g_Hhi + a_go[i] + k0, a_sz[i]);
                cp16(nb + O2_AL + a_sm[i], g_Hlo + a_go[i] + k0, a_sz[i]);
                cp16(nb + O2_BH + a_sm[i], g_DWhi + b_go[i] + k0, 16u);
                cp16(nb + O2_BL + a_sm[i], g_DWlo + b_go[i] + k0, 16u);
            }
            CP_COMMIT();
        }
        const uint32_t base = sb + (uint32_t)stage * G1_STAGE;

#pragma unroll
        for (int ks = 0; ks < 2; ks++) {
            uint32_t ah[2][4], al[2][4];
            ldsm4(ah[0], base + O2_AH + offA[0][ks]);
            ldsm4(ah[1], base + O2_AH + offA[1][ks]);
            ldsm4(al[0], base + O2_AL + offA[0][ks]);
            ldsm4(al[1], base + O2_AL + offA[1][ks]);
            uint32_t bh[4][4], bl[4][4];
#pragma unroll
            for (int p = 0; p < 4; p++) {
                ldsm4(bh[p], base + O2_BH + offB[p][ks]);
                ldsm4(bl[p], base + O2_BL + offB[p][ks]);
            }
#pragma unroll
            for (int mf = 0; mf < 2; mf++)
#pragma unroll
                for (int nf = 0; nf < 8; nf++) {
                    const int p = nf >> 1, q = (nf & 1) * 2;
                    mma16816(acc[mf][nf], ah[mf], bh[p][q], bh[p][q + 1]);
                    mma16816(acc[mf][nf], ah[mf], bl[p][q], bl[p][q + 1]);
                    mma16816(acc[mf][nf], al[mf], bh[p][q], bh[p][q + 1]);
                }
        }
        stage  = (stage  == 2) ? 0 : stage  + 1;
        pstage = (pstage == 2) ? 0 : pstage + 1;
    }

    // Gate-weighted combine via vector reduction (no return) — 2 fp32 per red
#pragma unroll
    for (int mf = 0; mf < 2; mf++)
#pragma unroll
        for (int half = 0; half < 2; half++) {
            int r = wm * 32 + mf * 16 + (lane >> 2) + half * 8;
            if (r < rem) {
                const int   tok = sh_tok[r];
                const float gt  = sh_gate[r];
                float* orow = out + (size_t)tok * DIM_K;
#pragma unroll
                for (int nf = 0; nf < 8; nf++) {
                    int col = k0out + wn * 64 + nf * 8 + (lane & 3) * 2;
                    float v0 = gt * acc[mf][nf][half * 2 + 0];
                    float v1 = gt * acc[mf][nf][half * 2 + 1];
                    asm volatile("red.global.add.v2.f32 [%0], {%1, %2};"
                                 :: "l"(orow + col), "f"(v0), "f"(v1) : "memory");
                }
            }
        }
}

// ---------------------------------------------------------------------------
// kernel_launch — graph-capturable (kernel launches only)
// Inputs: flat_h, flat_idx, flat_gate, gate_weight, up_weight, down_weight
// ---------------------------------------------------------------------------
extern "C" void kernel_launch(void* const* d_in, const int* in_sizes, int n_in,
                              void* d_out, int out_size) {
    const float* flat_h    = (const float*)d_in[0];
    const int*   flat_idx  = (const int*)  d_in[1];
    const float* flat_gate = (const float*)d_in[2];
    const float* gate_w    = (const float*)d_in[3];
    const float* up_w      = (const float*)d_in[4];
    const float* down_w    = (const float*)d_in[5];
    float*       out       = (float*)d_out;

    cudaFuncSetAttribute(gemm1_kernel, cudaFuncAttributeMaxDynamicSharedMemorySize, 3 * G1_STAGE);
    cudaFuncSetAttribute(gemm2_kernel, cudaFuncAttributeMaxDynamicSharedMemorySize, 3 * G1_STAGE);

    route_kernel<<<1, 256>>>(flat_idx);

    __nv_bfloat16 *Ahi, *Alo, *GWhi, *GWlo, *UWhi, *UWlo, *DWhi, *DWlo;
    cudaGetSymbolAddress((void**)&Ahi,  g_Ahi);  cudaGetSymbolAddress((void**)&Alo,  g_Alo);
    cudaGetSymbolAddress((void**)&GWhi, g_GWhi); cudaGetSymbolAddress((void**)&GWlo, g_GWlo);
    cudaGetSymbolAddress((void**)&UWhi, g_UWhi); cudaGetSymbolAddress((void**)&UWlo, g_UWlo);
    cudaGetSymbolAddress((void**)&DWhi, g_DWhi); cudaGetSymbolAddress((void**)&DWlo, g_DWlo);

    const int nA8 = (TOK_M * DIM_K) / 8;            // 524288
    const int nW8 = (NEXP * DIM_N * DIM_K) / 8;     // 2883584
    cvt_kernel<<<2048, 256>>>((const float4*)flat_h, (uint4*)Ahi,  (uint4*)Alo,  nA8);
    cvt_kernel<<<8192, 256>>>((const float4*)gate_w, (uint4*)GWhi, (uint4*)GWlo, nW8);
    cvt_kernel<<<8192, 256>>>((const float4*)up_w,   (uint4*)UWhi, (uint4*)UWlo, nW8);
    cvt_kernel<<<8192, 256>>>((const float4*)down_w, (uint4*)DWhi, (uint4*)DWlo, nW8);

    const int n4 = (TOK_M * DIM_K) / 4;
    zero_kernel<<<(n4 + 255) / 256, 256>>>((float4*)out, n4);

    dim3 g1(DIM_N / 64, MT, NEXP);    // (22, 8, 8)
    gemm1_kernel<<<g1, 256, 3 * G1_STAGE>>>();

    dim3 g2(DIM_K / 128, MT, NEXP);   // (16, 8, 8)
    gemm2_kernel<<<g2, 256, 3 * G1_STAGE>>>(flat_gate, out);
}

// round 16
// speedup vs baseline: 4.5985x; 1.4671x over previous
#include <cuda_runtime.h>
#include <cuda_fp16.h>
#include <stdint.h>
#include <math.h>

// ---------------------------------------------------------------------------
// Problem constants
// ---------------------------------------------------------------------------
#define TOK_M 2048
#define DIM_K 2048
#define DIM_N 1408
#define NEXP  8
#define NROWS 4096              // TOK_M * TOPK
#define BM    128               // CTA M tile
#define BK    32                // K chunk (fp16)
#define NCH1  (DIM_K/BK)        // 64
#define NCH2  (DIM_N/BK)        // 44
#define MT    8                 // m-tiles per expert (capacity 1024)

// ---------------------------------------------------------------------------
// Device scratch (static; no allocations anywhere)
// A (tokens) and H (intermediate) are EXACT fp16 splits (hi+lo).
// Weights are single fp16 (2^-11 rounding — the precision budget spend).
// ---------------------------------------------------------------------------
__device__ int g_sorted_row[NROWS];
__device__ int g_counts[NEXP];
__device__ int g_starts[NEXP];

__device__ __half g_Ah[(size_t)TOK_M * DIM_K];
__device__ __half g_Al[(size_t)TOK_M * DIM_K];
__device__ __half g_GW[(size_t)NEXP * DIM_N * DIM_K];
__device__ __half g_UW[(size_t)NEXP * DIM_N * DIM_K];
__device__ __half g_DW[(size_t)NEXP * DIM_K * DIM_N];
__device__ __half g_Hh[(size_t)NROWS * DIM_N];
__device__ __half g_Hl[(size_t)NROWS * DIM_N];

// ---------------------------------------------------------------------------
// Helpers (base-target instructions only)
// ---------------------------------------------------------------------------
__device__ __forceinline__ uint32_t smem_u32(const void* p) {
    uint32_t a;
    asm("{ .reg .u64 t; cvta.to.shared.u64 t, %1; cvt.u32.u64 %0, t; }" : "=r"(a) : "l"(p));
    return a;
}
__device__ __forceinline__ void cp16(uint32_t dst, const void* src, uint32_t sz) {
    asm volatile("cp.async.cg.shared.global [%0], [%1], 16, %2;"
                 :: "r"(dst), "l"(src), "r"(sz) : "memory");
}
#define CP_COMMIT() asm volatile("cp.async.commit_group;" ::: "memory")
#define CP_WAIT1()  asm volatile("cp.async.wait_group 1;" ::: "memory")
#define CP_WAIT0()  asm volatile("cp.async.wait_group 0;" ::: "memory")

__device__ __forceinline__ void ldsm4(uint32_t (&r)[4], uint32_t a) {
    asm volatile("ldmatrix.sync.aligned.m8n8.x4.shared.b16 {%0,%1,%2,%3}, [%4];"
                 : "=r"(r[0]), "=r"(r[1]), "=r"(r[2]), "=r"(r[3]) : "r"(a));
}
__device__ __forceinline__ void mma16816(float (&c)[4], const uint32_t (&a)[4],
                                         uint32_t b0, uint32_t b1) {
    asm volatile(
        "mma.sync.aligned.m16n8k16.row.col.f32.f16.f16.f32 "
        "{%0,%1,%2,%3}, {%4,%5,%6,%7}, {%8,%9}, {%0,%1,%2,%3};"
        : "+f"(c[0]), "+f"(c[1]), "+f"(c[2]), "+f"(c[3])
        : "r"(a[0]), "r"(a[1]), "r"(a[2]), "r"(a[3]), "r"(b0), "r"(b1));
}

// SMEM tile layout: row-major [rows][BK], 64B/row, XOR swizzle on 16B chunks.
#define SMOFF(row, c4) ((uint32_t)((row) * 64 + (((c4) ^ (((row) >> 1) & 3)) << 4)))

// ---------------------------------------------------------------------------
// Routing: stable counting sort by expert (1 block, 256 threads)
// ---------------------------------------------------------------------------
__global__ void route_kernel(const int* __restrict__ flat_idx) {
    __shared__ int sh_cnt[256][NEXP];
    __shared__ int sh_tot[NEXP];
    __shared__ int sh_start[NEXP];
    const int t = threadIdx.x, per = NROWS / 256, base = t * per;
    int local[NEXP];
#pragma unroll
    for (int e = 0; e < NEXP; e++) local[e] = 0;
    for (int i = 0; i < per; i++) local[flat_idx[base + i]]++;
#pragma unroll
    for (int e = 0; e < NEXP; e++) sh_cnt[t][e] = local[e];
    __syncthreads();
    if (t < NEXP) {
        int run = 0;
        for (int u = 0; u < 256; u++) { int v = sh_cnt[u][t]; sh_cnt[u][t] = run; run += v; }
        sh_tot[t] = run;
    }
    __syncthreads();
    if (t == 0) {
        int run = 0;
        for (int e = 0; e < NEXP; e++) {
            sh_start[e] = run; g_starts[e] = run; g_counts[e] = sh_tot[e]; run += sh_tot[e];
        }
    }
    __syncthreads();
    int off[NEXP];
#pragma unroll
    for (int e = 0; e < NEXP; e++) off[e] = sh_start[e] + sh_cnt[t][e];
    for (int i = 0; i < per; i++) {
        int e = flat_idx[base + i];
        g_sorted_row[off[e]++] = base + i;
    }
}

// ---------------------------------------------------------------------------
// fp32 -> (fp16 hi, fp16 lo) exact split; 8 elems/thread, streaming hints
// ---------------------------------------------------------------------------
__global__ void cvt_split_kernel(const float4* __restrict__ src,
                                 uint4* __restrict__ hi, uint4* __restrict__ lo, int n8) {
    for (int i = blockIdx.x * blockDim.x + threadIdx.x; i < n8; i += gridDim.x * blockDim.x) {
        float4 f0 = __ldcs(src + 2 * i);
        float4 f1 = __ldcs(src + 2 * i + 1);
        float v[8] = {f0.x, f0.y, f0.z, f0.w, f1.x, f1.y, f1.z, f1.w};
        uint32_t hw[4], lw[4];
#pragma unroll
        for (int p = 0; p < 4; p++) {
            __half h0 = __float2half_rn(v[2 * p]);
            __half h1 = __float2half_rn(v[2 * p + 1]);
            __half l0 = __float2half_rn(v[2 * p] - __half2float(h0));
            __half l1 = __float2half_rn(v[2 * p + 1] - __half2float(h1));
            hw[p] = (uint32_t)__half_as_ushort(h0) | ((uint32_t)__half_as_ushort(h1) << 16);
            lw[p] = (uint32_t)__half_as_ushort(l0) | ((uint32_t)__half_as_ushort(l1) << 16);
        }
        __stcs(hi + i, make_uint4(hw[0], hw[1], hw[2], hw[3]));
        __stcs(lo + i, make_uint4(lw[0], lw[1], lw[2], lw[3]));
    }
}

// fp32 -> fp16 single (weights); 8 elems/thread
__global__ void cvt_single_kernel(const float4* __restrict__ src,
                                  uint4* __restrict__ dst, int n8) {
    for (int i = blockIdx.x * blockDim.x + threadIdx.x; i < n8; i += gridDim.x * blockDim.x) {
        float4 f0 = __ldcs(src + 2 * i);
        float4 f1 = __ldcs(src + 2 * i + 1);
        float v[8] = {f0.x, f0.y, f0.z, f0.w, f1.x, f1.y, f1.z, f1.w};
        uint32_t w[4];
#pragma unroll
        for (int p = 0; p < 4; p++) {
            __half h0 = __float2half_rn(v[2 * p]);
            __half h1 = __float2half_rn(v[2 * p + 1]);
            w[p] = (uint32_t)__half_as_ushort(h0) | ((uint32_t)__half_as_ushort(h1) << 16);
        }
        __stcs(dst + i, make_uint4(w[0], w[1], w[2], w[3]));
    }
}

__global__ void zero_kernel(float4* __restrict__ p, int n4) {
    int i = blockIdx.x * blockDim.x + threadIdx.x;
    if (i < n4) p[i] = make_float4(0.f, 0.f, 0.f, 0.f);
}

// ---------------------------------------------------------------------------
// GEMM1: gate+up, 2-pass (Ah·W + Al·W) + SwiGLU epilogue -> split-fp16 H
// CTA tile 128(M) x 64(N) x 32(K). 8 warps (4x2), warp tile 32x32 per matrix.
// Stage: Ah 8K, Al 8K, G 4K, U 4K = 24KB; 3 stages, prefetch distance 2.
// ---------------------------------------------------------------------------
#define G1_STAGE 24576
#define O_AH 0
#define O_AL 8192
#define O_G  16384
#define O_U  20480

__global__ __launch_bounds__(256, 2)
void gemm1_kernel() {
    const int e   = blockIdx.z;
    const int cnt = g_counts[e];
    const int m0  = blockIdx.y * BM;
    if (m0 >= cnt) return;
    const int n0    = blockIdx.x * 64;
    const int start = g_starts[e];
    const int tid   = threadIdx.x;
    const int lane  = tid & 31, wid = tid >> 5;
    const int wm = wid & 3, wn = wid >> 2;

    extern __shared__ char smem[];
    const uint32_t sb = smem_u32(smem);

    __shared__ int sh_tok[BM];
    if (tid < BM) {
        int m = m0 + tid;
        sh_tok[tid] = (m < cnt) ? (g_sorted_row[start + m] >> 1) : -1;
    }
    __syncthreads();

    // ---- global->smem geometry
    uint32_t a_sm[2], a_sz[2];
    size_t   a_go[2];
#pragma unroll
    for (int i = 0; i < 2; i++) {
        int idx = tid + i * 256;
        int row = idx >> 2, c4 = idx & 3;
        a_sm[i] = SMOFF(row, c4);
        int tok = sh_tok[row];
        a_sz[i] = (tok >= 0) ? 16u : 0u;
        a_go[i] = (size_t)(tok >= 0 ? tok : 0) * DIM_K + c4 * 8;
    }
    const int brow = tid >> 2, bc4 = tid & 3;              // B rows 0..63
    const uint32_t b_sm = SMOFF(brow, bc4);
    const size_t   b_go = ((size_t)e * DIM_N + n0 + brow) * DIM_K + bc4 * 8;

    // ---- ldmatrix offsets
    uint32_t offA[2][2], offB[2][2];
#pragma unroll
    for (int mf = 0; mf < 2; mf++)
#pragma unroll
        for (int ks = 0; ks < 2; ks++) {
            int row = wm * 32 + mf * 16 + (lane & 15);
            int c4  = ks * 2 + (lane >> 4);
            offA[mf][ks] = SMOFF(row, c4);
        }
#pragma unroll
    for (int p = 0; p < 2; p++)
#pragma unroll
        for (int ks = 0; ks < 2; ks++) {
            int row = wn * 32 + p * 16 + ((lane >> 4) & 1) * 8 + (lane & 7);
            int c4  = ks * 2 + ((lane >> 3) & 1);
            offB[p][ks] = SMOFF(row, c4);
        }

    float accG[2][4][4], accU[2][4][4];
#pragma unroll
    for (int mf = 0; mf < 2; mf++)
#pragma unroll
        for (int nf = 0; nf < 4; nf++)
#pragma unroll
            for (int q = 0; q < 4; q++) { accG[mf][nf][q] = 0.f; accU[mf][nf][q] = 0.f; }

    // prologue: stages 0,1
#pragma unroll
    for (int pc = 0; pc < 2; pc++) {
        const uint32_t nb = sb + (uint32_t)pc * G1_STAGE;
        const int k0 = pc * BK;
#pragma unroll
        for (int i = 0; i < 2; i++) {
            cp16(nb + O_AH + a_sm[i], g_Ah + a_go[i] + k0, a_sz[i]);
            cp16(nb + O_AL + a_sm[i], g_Al + a_go[i] + k0, a_sz[i]);
        }
        cp16(nb + O_G + b_sm, g_GW + b_go + k0, 16u);
        cp16(nb + O_U + b_sm, g_UW + b_go + k0, 16u);
        CP_COMMIT();
    }

    int stage = 0, pstage = 2;
    for (int c = 0; c < NCH1; c++) {
        if (c == NCH1 - 1) { CP_WAIT0(); } else { CP_WAIT1(); }
        __syncthreads();
        if (c + 2 < NCH1) {
            const uint32_t nb = sb + (uint32_t)pstage * G1_STAGE;
            const int k0 = (c + 2) * BK;
#pragma unroll
            for (int i = 0; i < 2; i++) {
                cp16(nb + O_AH + a_sm[i], g_Ah + a_go[i] + k0, a_sz[i]);
                cp16(nb + O_AL + a_sm[i], g_Al + a_go[i] + k0, a_sz[i]);
            }
            cp16(nb + O_G + b_sm, g_GW + b_go + k0, 16u);
            cp16(nb + O_U + b_sm, g_UW + b_go + k0, 16u);
            CP_COMMIT();
        }
        const uint32_t base = sb + (uint32_t)stage * G1_STAGE;

#pragma unroll
        for (int ks = 0; ks < 2; ks++) {
            uint32_t ah[2][4], al[2][4];
            ldsm4(ah[0], base + O_AH + offA[0][ks]);
            ldsm4(ah[1], base + O_AH + offA[1][ks]);
            ldsm4(al[0], base + O_AL + offA[0][ks]);
            ldsm4(al[1], base + O_AL + offA[1][ks]);
            uint32_t gB[2][4], uB[2][4];
#pragma unroll
            for (int p = 0; p < 2; p++) {
                ldsm4(gB[p], base + O_G + offB[p][ks]);
                ldsm4(uB[p], base + O_U + offB[p][ks]);
            }
#pragma unroll
            for (int mf = 0; mf < 2; mf++)
#pragma unroll
                for (int nf = 0; nf < 4; nf++) {
                    const int p = nf >> 1, q = (nf & 1) * 2;
                    mma16816(accG[mf][nf], ah[mf], gB[p][q], gB[p][q + 1]);
                    mma16816(accG[mf][nf], al[mf], gB[p][q], gB[p][q + 1]);
                    mma16816(accU[mf][nf], ah[mf], uB[p][q], uB[p][q + 1]);
                    mma16816(accU[mf][nf], al[mf], uB[p][q], uB[p][q + 1]);
                }
        }
        stage  = (stage  == 2) ? 0 : stage  + 1;
        pstage = (pstage == 2) ? 0 : pstage + 1;
    }

    // SwiGLU epilogue -> split-fp16 H
    const int rem = cnt - m0;
#pragma unroll
    for (int mf = 0; mf < 2; mf++)
#pragma unroll
        for (int half = 0; half < 2; half++) {
            int r = wm * 32 + mf * 16 + (lane >> 2) + half * 8;
            if (r < rem) {
                size_t s = (size_t)(start + m0 + r);
#pragma unroll
                for (int nf = 0; nf < 4; nf++) {
                    float g0 = fminf(accG[mf][nf][half * 2 + 0], 10.f);
                    float g1 = fminf(accG[mf][nf][half * 2 + 1], 10.f);
                    float u0 = fminf(fmaxf(accU[mf][nf][half * 2 + 0], -10.f), 10.f);
                    float u1 = fminf(fmaxf(accU[mf][nf][half * 2 + 1], -10.f), 10.f);
                    float h0 = g0 / (1.f + __expf(-g0)) * u0;
                    float h1 = g1 / (1.f + __expf(-g1)) * u1;
                    __half a0 = __float2half_rn(h0), a1 = __float2half_rn(h1);
                    __half b0 = __float2half_rn(h0 - __half2float(a0));
                    __half b1 = __float2half_rn(h1 - __half2float(a1));
                    int col = n0 + wn * 32 + nf * 8 + (lane & 3) * 2;
                    uint32_t hv = (uint32_t)__half_as_ushort(a0) | ((uint32_t)__half_as_ushort(a1) << 16);
                    uint32_t lv = (uint32_t)__half_as_ushort(b0) | ((uint32_t)__half_as_ushort(b1) << 16);
                    *(uint32_t*)(g_Hh + s * DIM_N + col) = hv;
                    *(uint32_t*)(g_Hl + s * DIM_N + col) = lv;
                }
            }
        }
}

// ---------------------------------------------------------------------------
// GEMM2: down GEMM, 2-pass (Hh·W + Hl·W) + fused gate-weighted red combine
// CTA tile 128(M) x 128(Nout) x 32(K=DIM_N). 8 warps (4x2), warp tile 32x64.
// Stage: Hh 8K, Hl 8K, B 8K = 24KB; 3 stages, prefetch distance 2.
// ---------------------------------------------------------------------------
#define O2_AH 0
#define O2_AL 8192
#define O2_B  16384

__global__ __launch_bounds__(256, 2)
void gemm2_kernel(const float* __restrict__ flat_gate, float* __restrict__ out) {
    const int e   = blockIdx.z;
    const int cnt = g_counts[e];
    const int m0  = blockIdx.y * BM;
    if (m0 >= cnt) return;
    const int k0out = blockIdx.x * 128;
    const int start = g_starts[e];
    const int tid   = threadIdx.x;
    const int lane  = tid & 31, wid = tid >> 5;
    const int wm = wid & 3, wn = wid >> 2;
    const int rem = cnt - m0;

    extern __shared__ char smem[];
    const uint32_t sb = smem_u32(smem);

    __shared__ int   sh_tok[BM];
    __shared__ float sh_gate[BM];
    if (tid < BM) {
        int m = m0 + tid;
        if (m < cnt) {
            int r = g_sorted_row[start + m];
            sh_tok[tid] = r >> 1; sh_gate[tid] = flat_gate[r];
        } else { sh_tok[tid] = 0; sh_gate[tid] = 0.f; }
    }
    __syncthreads();

    uint32_t a_sm[2], a_sz[2];
    size_t   a_go[2], b_go[2];
#pragma unroll
    for (int i = 0; i < 2; i++) {
        int idx = tid + i * 256;
        int row = idx >> 2, c4 = idx & 3;
        a_sm[i] = SMOFF(row, c4);
        bool v  = (row < rem);
        a_sz[i] = v ? 16u : 0u;
        a_go[i] = (size_t)(start + m0 + (v ? row : 0)) * DIM_N + c4 * 8;
        b_go[i] = ((size_t)e * DIM_K + k0out + row) * DIM_N + c4 * 8;
    }

    uint32_t offA[2][2], offB[4][2];
#pragma unroll
    for (int mf = 0; mf < 2; mf++)
#pragma unroll
        for (int ks = 0; ks < 2; ks++) {
            int row = wm * 32 + mf * 16 + (lane & 15);
            int c4  = ks * 2 + (lane >> 4);
            offA[mf][ks] = SMOFF(row, c4);
        }
#pragma unroll
    for (int p = 0; p < 4; p++)
#pragma unroll
        for (int ks = 0; ks < 2; ks++) {
            int row = wn * 64 + p * 16 + ((lane >> 4) & 1) * 8 + (lane & 7);
            int c4  = ks * 2 + ((lane >> 3) & 1);
            offB[p][ks] = SMOFF(row, c4);
        }

    float acc[2][8][4];
#pragma unroll
    for (int mf = 0; mf < 2; mf++)
#pragma unroll
        for (int nf = 0; nf < 8; nf++)
#pragma unroll
            for (int q = 0; q < 4; q++) acc[mf][nf][q] = 0.f;

    // prologue: stages 0,1
#pragma unroll
    for (int pc = 0; pc < 2; pc++) {
        const uint32_t nb = sb + (uint32_t)pc * G1_STAGE;
        const int k0 = pc * BK;
#pragma unroll
        for (int i = 0; i < 2; i++) {
            cp16(nb + O2_AH + a_sm[i], g_Hh + a_go[i] + k0, a_sz[i]);
            cp16(nb + O2_AL + a_sm[i], g_Hl + a_go[i] + k0, a_sz[i]);
            cp16(nb + O2_B  + a_sm[i], g_DW + b_go[i] + k0, 16u);
        }
        CP_COMMIT();
    }

    int stage = 0, pstage = 2;
    for (int c = 0; c < NCH2; c++) {
        if (c == NCH2 - 1) { CP_WAIT0(); } else { CP_WAIT1(); }
        __syncthreads();
        if (c + 2 < NCH2) {
            const uint32_t nb = sb + (uint32_t)pstage * G1_STAGE;
            const int k0 = (c + 2) * BK;
#pragma unroll
            for (int i = 0; i < 2; i++) {
                cp16(nb + O2_AH + a_sm[i], g_Hh + a_go[i] + k0, a_sz[i]);
                cp16(nb + O2_AL + a_sm[i], g_Hl + a_go[i] + k0, a_sz[i]);
                cp16(nb + O2_B  + a_sm[i], g_DW + b_go[i] + k0, 16u);
            }
            CP_COMMIT();
        }
        const uint32_t base = sb + (uint32_t)stage * G1_STAGE;

#pragma unroll
        for (int ks = 0; ks < 2; ks++) {
            uint32_t ah[2][4], al[2][4];
            ldsm4(ah[0], base + O2_AH + offA[0][ks]);
            ldsm4(ah[1], base + O2_AH + offA[1][ks]);
            ldsm4(al[0], base + O2_AL + offA[0][ks]);
            ldsm4(al[1], base + O2_AL + offA[1][ks]);
            uint32_t bB[4][4];
#pragma unroll
            for (int p = 0; p < 4; p++)
                ldsm4(bB[p], base + O2_B + offB[p][ks]);
#pragma unroll
            for (int mf = 0; mf < 2; mf++)
#pragma unroll
                for (int nf = 0; nf < 8; nf++) {
                    const int p = nf >> 1, q = (nf & 1) * 2;
                    mma16816(acc[mf][nf], ah[mf], bB[p][q], bB[p][q + 1]);
                    mma16816(acc[mf][nf], al[mf], bB[p][q], bB[p][q + 1]);
                }
        }
        stage  = (stage  == 2) ? 0 : stage  + 1;
        pstage = (pstage == 2) ? 0 : pstage + 1;
    }

    // Gate-weighted combine via vector reduction (no return) — 2 fp32 per red
#pragma unroll
    for (int mf = 0; mf < 2; mf++)
#pragma unroll
        for (int half = 0; half < 2; half++) {
            int r = wm * 32 + mf * 16 + (lane >> 2) + half * 8;
            if (r < rem) {
                const int   tok = sh_tok[r];
                const float gt  = sh_gate[r];
                float* orow = out + (size_t)tok * DIM_K;
#pragma unroll
                for (int nf = 0; nf < 8; nf++) {
                    int col = k0out + wn * 64 + nf * 8 + (lane & 3) * 2;
                    float v0 = gt * acc[mf][nf][half * 2 + 0];
                    float v1 = gt * acc[mf][nf][half * 2 + 1];
                    asm volatile("red.global.add.v2.f32 [%0], {%1, %2};"
                                 :: "l"(orow + col), "f"(v0), "f"(v1) : "memory");
                }
            }
        }
}

// ---------------------------------------------------------------------------
// kernel_launch — graph-capturable (kernel launches only)
// Inputs: flat_h, flat_idx, flat_gate, gate_weight, up_weight, down_weight
// ---------------------------------------------------------------------------
extern "C" void kernel_launch(void* const* d_in, const int* in_sizes, int n_in,
                              void* d_out, int out_size) {
    const float* flat_h    = (const float*)d_in[0];
    const int*   flat_idx  = (const int*)  d_in[1];
    const float* flat_gate = (const float*)d_in[2];
    const float* gate_w    = (const float*)d_in[3];
    const float* up_w      = (const float*)d_in[4];
    const float* down_w    = (const float*)d_in[5];
    float*       out       = (float*)d_out;

    cudaFuncSetAttribute(gemm1_kernel, cudaFuncAttributeMaxDynamicSharedMemorySize, 3 * G1_STAGE);
    cudaFuncSetAttribute(gemm2_kernel, cudaFuncAttributeMaxDynamicSharedMemorySize, 3 * G1_STAGE);

    route_kernel<<<1, 256>>>(flat_idx);

    __half *Ah, *Al, *GW, *UW, *DW;
    cudaGetSymbolAddress((void**)&Ah, g_Ah); cudaGetSymbolAddress((void**)&Al, g_Al);
    cudaGetSymbolAddress((void**)&GW, g_GW); cudaGetSymbolAddress((void**)&UW, g_UW);
    cudaGetSymbolAddress((void**)&DW, g_DW);

    const int nA8 = (TOK_M * DIM_K) / 8;            // 524288
    const int nW8 = (NEXP * DIM_N * DIM_K) / 8;     // 2883584
    cvt_split_kernel<<<2048, 256>>>((const float4*)flat_h, (uint4*)Ah, (uint4*)Al, nA8);
    cvt_single_kernel<<<8192, 256>>>((const float4*)gate_w, (uint4*)GW, nW8);
    cvt_single_kernel<<<8192, 256>>>((const float4*)up_w,   (uint4*)UW, nW8);
    cvt_single_kernel<<<8192, 256>>>((const float4*)down_w, (uint4*)DW, nW8);

    const int n4 = (TOK_M * DIM_K) / 4;
    zero_kernel<<<(n4 + 255) / 256, 256>>>((float4*)out, n4);

    dim3 g1(DIM_N / 64, MT, NEXP);    // (22, 8, 8)
    gemm1_kernel<<<g1, 256, 3 * G1_STAGE>>>();

    dim3 g2(DIM_K / 128, MT, NEXP);   // (16, 8, 8)
    gemm2_kernel<<<g2, 256, 3 * G1_STAGE>>>(flat_gate, out);
}